// round 14
// baseline (speedup 1.0000x reference)
#include <cuda_runtime.h>
#include <cuda_bf16.h>
#include <cstdint>

// Flatten 2x2 blocks:
//   out[bc, i*1024 + 4j + 2r + s] = x[bc, 2i+r, 2j+s]
// x: (32, 3, 512, 512) fp32. bc in [0,96), i in [0,256), j in [0,256).
//
// R14: 256-bit transactions BOTH directions at the confirmed geometry
// optimum (3072 CTAs x 1024 threads, contiguous 32 KB strips).
// Lane pairing (xor 1): even lane v8-loads row 2i cols [8q, 8q+8), odd
// lane v8-loads row 2i+1 same cols. 4 butterfly shuffles exchange the
// cross halves; each lane then owns one 32 B output span:
//   even lane: out j = 4q, 4q+1   -> {r0[0..3] interleaved with r1[0..3]}
//   odd  lane: out j = 4q+2, 4q+3 -> {r0[4..7] interleaved with r1[4..7]}
// One st.global.v8.f32 per lane. Per 32 B out: 1 LDG.256 + 4 SHFL +
// 1 STG.256 (issue util is ~10%, shuffles are free).

__global__ __launch_bounds__(1024)
void flatten2x2_kernel(const float* __restrict__ x, float* __restrict__ out) {
    unsigned tid = threadIdx.x;                 // 0..1023
    unsigned p   = tid & 1u;                    // row parity within pair
    unsigned q   = (tid >> 1) & 63u;            // column-octet index 0..63
    unsigned di  = tid >> 7;                    // 0..7: i slot within strip
    unsigned blk = blockIdx.x;                  // 0..3071
    unsigned i   = (blk & 31u) * 8u + di;       // i in [0,256)
    unsigned bc  = blk >> 5;                    // 0..95

    // load: row 2i + p, cols 8q .. 8q+7  (one 256-bit load)
    const float* lp = x + (size_t)bc * 262144u + (size_t)(2u * i + p) * 512u + 8u * q;
    float r[8];
    asm volatile("ld.global.nc.v8.f32 {%0,%1,%2,%3,%4,%5,%6,%7}, [%8];"
                 : "=f"(r[0]), "=f"(r[1]), "=f"(r[2]), "=f"(r[3]),
                   "=f"(r[4]), "=f"(r[5]), "=f"(r[6]), "=f"(r[7])
                 : "l"(lp));

    // exchange cross halves with the partner lane (xor 1):
    // even lane sends r[4..7] (row-2i cols 8q+4..), receives partner's
    // r[0..3] (row-2i+1 cols 8q..); odd lane symmetric.
    float o[4];
    #pragma unroll
    for (int m = 0; m < 4; m++) {
        float src = p ? r[m] : r[4 + m];
        o[m] = __shfl_xor_sync(0xFFFFFFFFu, src, 1);
    }
    // even lane: row0 = r[0..3], row1 = o[0..3]
    // odd  lane: row0 = o[0..3], row1 = r[4..7]
    float t0 = p ? o[0] : r[0];
    float t1 = p ? o[1] : r[1];
    float t2 = p ? o[2] : r[2];
    float t3 = p ? o[3] : r[3];
    float u0 = p ? r[4] : o[0];
    float u1 = p ? r[5] : o[1];
    float u2 = p ? r[6] : o[2];
    float u3 = p ? r[7] : o[3];

    // output span: j = 4q + 2p, 4q + 2p + 1 -> floats [i*1024 + 16q + 8p, +8)
    // layout per j: {row0[2j], row0[2j+1], row1[2j], row1[2j+1]}
    float* op = out + (size_t)bc * 262144u + (size_t)i * 1024u + 16u * q + 8u * p;
    asm volatile("st.global.v8.f32 [%0], {%1,%2,%3,%4,%5,%6,%7,%8};"
                 :: "l"(op),
                    "f"(t0), "f"(t1), "f"(u0), "f"(u1),
                    "f"(t2), "f"(t3), "f"(u2), "f"(u3)
                 : "memory");
}

extern "C" void kernel_launch(void* const* d_in, const int* in_sizes, int n_in,
                              void* d_out, int out_size) {
    const float* x = (const float*)d_in[0];
    float* out = (float*)d_out;

    // 96 images x 32 strips (8 i-values each) = 3072 CTAs, 1024 threads
    flatten2x2_kernel<<<3072, 1024>>>(x, out);
}

// round 15
// speedup vs baseline: 1.0471x; 1.0471x over previous
#include <cuda_runtime.h>
#include <cuda_bf16.h>
#include <cstdint>

// Flatten 2x2 blocks:
//   out[bc, i*1024 + 4j + 2r + s] = x[bc, 2i+r, 2j+s]
// x: (32, 3, 512, 512) fp32. bc in [0,96), i in [0,256), j in [0,256).
//
// FINAL (R13 variant, confirmation run). The task is pinned at the
// sustained mixed-R/W DRAM floor: 201 MB compulsory traffic per graph
// replay (bijective permutation of random data; working set 201 MB >
// 126 MB L2; evict_last/evict_first policy hints proved inert without
// the persisting-L2 carveout, which the harness forbids).
//
// Confirmed levers:
//  - geometry: 3072 CTAs x 1024 threads, each CTA one contiguous 32 KB
//    in / 32 KB out strip (34.5-34.9 vs >=35.3 for 256/512-thr blocks,
//    fatter strips, or persistent grids; best sample 33.28).
//  - Blackwell 256-bit stores (st.global.v8.f32): best profiled HBM of
//    the session (5616 GB/s, DRAM 70.9%).
// Dead ends (bench-neutral or worse): MLP scaling, L2 policies, burst
// reordering, persistent single-wave, v8 loads + lane shuffles.
//
// Per thread: 2 coalesced LDG.128 (rows 2i, 2i+1) + 1 STG.256 covering
// two consecutive output float4s:
//   out f4 (i, 2j0)   = {a.x, a.y, b.x, b.y}
//   out f4 (i, 2j0+1) = {a.z, a.w, b.z, b.w}

__global__ __launch_bounds__(1024)
void flatten2x2_kernel(const float4* __restrict__ x4, float4* __restrict__ out4) {
    unsigned tid = threadIdx.x;                 // 0..1023
    unsigned j0  = tid & 127u;                  // j-pair index: j = 2*j0, 2*j0+1
    unsigned di  = tid >> 7;                    // 0..7: i slot within strip
    unsigned blk = blockIdx.x;                  // 0..3071
    unsigned i   = (blk & 31u) * 8u + di;       // i in [0,256)
    unsigned bc  = blk >> 5;                    // 0..95

    // input as float4: row stride 128, image stride 512*128 = 65536
    const float4* base = x4 + (size_t)bc * 65536u + (size_t)(2u * i) * 128u + j0;
    float4 a = __ldg(base);          // row 2i,   cols 4j0..4j0+3
    float4 b = __ldg(base + 128u);   // row 2i+1, cols 4j0..4j0+3

    // output: float4 units, i stride 256, image stride 65536
    float4* op = out4 + (size_t)bc * 65536u + (size_t)i * 256u + 2u * j0;
    asm volatile(
        "st.global.v8.f32 [%0], {%1,%2,%3,%4,%5,%6,%7,%8};"
        :: "l"(op),
           "f"(a.x), "f"(a.y), "f"(b.x), "f"(b.y),
           "f"(a.z), "f"(a.w), "f"(b.z), "f"(b.w)
        : "memory");
}

extern "C" void kernel_launch(void* const* d_in, const int* in_sizes, int n_in,
                              void* d_out, int out_size) {
    const float4* x4 = (const float4*)d_in[0];
    float4* out4 = (float4*)d_out;

    // 96 images x 32 strips (8 i-values each) = 3072 CTAs, 1024 threads
    flatten2x2_kernel<<<3072, 1024>>>(x4, out4);
}